// round 8
// baseline (speedup 1.0000x reference)
#include <cuda_runtime.h>
#include <cuda_bf16.h>
#include <cstdint>

// Problem shape (fixed by reference setup_inputs)
static constexpr int NB = 16;
static constexpr int TQ = 2048;
static constexpr int TS = 2048;
static constexpr int HD = 1024;

// ---------------------------------------------------------------------------
// Static device scratch (no allocations allowed)
// ---------------------------------------------------------------------------
__device__ float g_scores[(size_t)NB * TQ * TS];                    // 256 MB
__device__ __nv_bfloat16 g_Hh[(size_t)NB * TQ * HD];
__device__ __nv_bfloat16 g_Hm[(size_t)NB * TQ * HD];
__device__ __nv_bfloat16 g_Eh[(size_t)NB * TS * HD];
__device__ __nv_bfloat16 g_Em[(size_t)NB * TS * HD];
__device__ __nv_bfloat16 g_ETh[(size_t)NB * HD * TS];               // enc^T
__device__ __nv_bfloat16 g_ETm[(size_t)NB * HD * TS];
__device__ __nv_bfloat16 g_Ph[(size_t)NB * TQ * TS];
__device__ __nv_bfloat16 g_Pm[(size_t)NB * TQ * TS];

// ---------------------------------------------------------------------------
// helpers
// ---------------------------------------------------------------------------
__device__ __forceinline__ void split4(float4 v, uint2& hi, uint2& mid) {
    __nv_bfloat162 h01 = __floats2bfloat162_rn(v.x, v.y);
    __nv_bfloat162 h23 = __floats2bfloat162_rn(v.z, v.w);
    float2 f01 = __bfloat1622float2(h01);
    float2 f23 = __bfloat1622float2(h23);
    __nv_bfloat162 m01 = __floats2bfloat162_rn(v.x - f01.x, v.y - f01.y);
    __nv_bfloat162 m23 = __floats2bfloat162_rn(v.z - f23.x, v.w - f23.y);
    hi.x  = *reinterpret_cast<uint32_t*>(&h01);
    hi.y  = *reinterpret_cast<uint32_t*>(&h23);
    mid.x = *reinterpret_cast<uint32_t*>(&m01);
    mid.y = *reinterpret_cast<uint32_t*>(&m23);
}

__device__ __forceinline__ void cpasync16(uint32_t dst, const void* src) {
    asm volatile("cp.async.cg.shared.global [%0], [%1], 16;\n" :: "r"(dst), "l"(src));
}

__device__ __forceinline__ void mma16(float c[4], const uint32_t a[4],
                                      uint32_t b0, uint32_t b1) {
    asm volatile(
        "mma.sync.aligned.m16n8k16.row.col.f32.bf16.bf16.f32 "
        "{%0,%1,%2,%3}, {%4,%5,%6,%7}, {%8,%9}, {%0,%1,%2,%3};\n"
        : "+f"(c[0]), "+f"(c[1]), "+f"(c[2]), "+f"(c[3])
        : "r"(a[0]), "r"(a[1]), "r"(a[2]), "r"(a[3]), "r"(b0), "r"(b1));
}

__device__ __forceinline__ void ldsm4(uint32_t r[4], uint32_t addr) {
    asm volatile("ldmatrix.sync.aligned.m8n8.x4.shared.b16 {%0,%1,%2,%3}, [%4];"
                 : "=r"(r[0]), "=r"(r[1]), "=r"(r[2]), "=r"(r[3]) : "r"(addr));
}

// ============================================================================
// prep: split hid/enc into bf16 hi+mid
// ============================================================================
__global__ void __launch_bounds__(256)
convert_kernel(const float* __restrict__ hid, const float* __restrict__ enc) {
    size_t i = ((size_t)blockIdx.x * 256 + threadIdx.x) * 4;
    float4 h = *reinterpret_cast<const float4*>(hid + i);
    uint2 hh, hm;
    split4(h, hh, hm);
    *reinterpret_cast<uint2*>(g_Hh + i) = hh;
    *reinterpret_cast<uint2*>(g_Hm + i) = hm;
    float4 e = *reinterpret_cast<const float4*>(enc + i);
    uint2 eh, em;
    split4(e, eh, em);
    *reinterpret_cast<uint2*>(g_Eh + i) = eh;
    *reinterpret_cast<uint2*>(g_Em + i) = em;
}

// ============================================================================
// prep: enc[b][s][h] -> encT hi/mid [b][h][s]   (K-major B operand for K3)
// ============================================================================
__global__ void __launch_bounds__(256)
transpose_kernel(const float* __restrict__ enc) {
    __shared__ float tile[32][33];
    const int b = blockIdx.z;
    const int s0 = blockIdx.x * 32, h0 = blockIdx.y * 32;
    const int tx = threadIdx.x & 31, ty = threadIdx.x >> 5;
    const float* src = enc + (size_t)b * TS * HD;
    #pragma unroll
    for (int j = 0; j < 32; j += 8)
        tile[ty + j][tx] = src[(size_t)(s0 + ty + j) * HD + h0 + tx];
    __syncthreads();
    #pragma unroll
    for (int j = 0; j < 32; j += 8) {
        int r = ty + j;                       // h_local
        float v = tile[tx][r];                // enc[s0+tx][h0+r]
        __nv_bfloat16 hb = __float2bfloat16(v);
        __nv_bfloat16 mb = __float2bfloat16(v - __bfloat162float(hb));
        size_t o = (size_t)b * HD * TS + (size_t)(h0 + r) * TS + s0 + tx;
        g_ETh[o] = hb;
        g_ETm[o] = mb;
    }
}

// ============================================================================
// generic mma.sync GEMM: C[M,N] = (Ah+Am)*(Bh+Bm)^T, 3 split terms.
// A: [M][K] K-contig, B: [N][K] K-contig, both pre-split bf16.
// Block tile 128x256, BK=32, 8 warps (2x4), warp tile 64x64.
// smem rows padded to 80B (32 bf16 + 8 pad) -> conflict-free ldmatrix.
// double-buffered cp.async pipeline.
// ============================================================================
static constexpr int ST_AH = 0;
static constexpr int ST_AM = 10240;    // 128*80
static constexpr int ST_BH = 20480;
static constexpr int ST_BM = 40960;    // +256*80
static constexpr int STAGE = 61440;
static constexpr int GEMM_SMEM = 2 * STAGE;   // 122880

__global__ void __launch_bounds__(256, 1)
gemm_kernel(const __nv_bfloat16* __restrict__ Ah, const __nv_bfloat16* __restrict__ Am,
            const __nv_bfloat16* __restrict__ Bh, const __nv_bfloat16* __restrict__ Bm,
            float* __restrict__ C, int K, int ldc,
            size_t batA, size_t batB, size_t batC) {
    extern __shared__ __align__(128) char smem[];
    const uint32_t sb = (uint32_t)__cvta_generic_to_shared(smem);
    const int tid  = threadIdx.x;
    const int lane = tid & 31;
    const int wid  = tid >> 5;
    const int bz = blockIdx.z;
    const int bM = blockIdx.y * 128;
    const int bN = blockIdx.x * 256;
    const int wm = (wid >> 2) * 64;
    const int wn = (wid & 3) * 64;
    const int tg = lane & 3;
    const int gp = lane >> 2;

    const __nv_bfloat16* pAh = Ah + (size_t)bz * batA + (size_t)bM * K;
    const __nv_bfloat16* pAm = Am + (size_t)bz * batA + (size_t)bM * K;
    const __nv_bfloat16* pBh = Bh + (size_t)bz * batB + (size_t)bN * K;
    const __nv_bfloat16* pBm = Bm + (size_t)bz * batB + (size_t)bN * K;

    // ldmatrix per-lane base byte offsets (row-major padded tiles)
    const uint32_t aOff = (uint32_t)(wm + (lane & 15)) * 80u + (uint32_t)(lane >> 4) * 16u;
    const uint32_t bOff = (uint32_t)(wn + (lane & 15)) * 80u + (uint32_t)(lane >> 4) * 16u;

    float acc[4][8][4];
    #pragma unroll
    for (int i = 0; i < 4; i++)
        #pragma unroll
        for (int j = 0; j < 8; j++)
            #pragma unroll
            for (int k = 0; k < 4; k++) acc[i][j][k] = 0.f;

    const int KT = K >> 5;

    // -------- prologue: prefetch tile 0 --------
    {
        const int k0 = 0;
        #pragma unroll
        for (int i = 0; i < 2; i++) {
            int id = tid + (i << 8);
            int r = id >> 2, c = id & 3;
            uint32_t d = sb + (uint32_t)(r * 80 + c * 16);
            cpasync16(d + ST_AH, pAh + (size_t)r * K + k0 + c * 8);
            cpasync16(d + ST_AM, pAm + (size_t)r * K + k0 + c * 8);
        }
        #pragma unroll
        for (int i = 0; i < 4; i++) {
            int id = tid + (i << 8);
            int r = id >> 2, c = id & 3;
            uint32_t d = sb + (uint32_t)(r * 80 + c * 16);
            cpasync16(d + ST_BH, pBh + (size_t)r * K + k0 + c * 8);
            cpasync16(d + ST_BM, pBm + (size_t)r * K + k0 + c * 8);
        }
        asm volatile("cp.async.commit_group;" ::: "memory");
    }

    for (int kt = 0; kt < KT; kt++) {
        // prefetch next tile into the other buffer
        if (kt + 1 < KT) {
            const int k0 = (kt + 1) << 5;
            const uint32_t stb = sb + (uint32_t)(((kt + 1) & 1) * STAGE);
            #pragma unroll
            for (int i = 0; i < 2; i++) {
                int id = tid + (i << 8);
                int r = id >> 2, c = id & 3;
                uint32_t d = stb + (uint32_t)(r * 80 + c * 16);
                cpasync16(d + ST_AH, pAh + (size_t)r * K + k0 + c * 8);
                cpasync16(d + ST_AM, pAm + (size_t)r * K + k0 + c * 8);
            }
            #pragma unroll
            for (int i = 0; i < 4; i++) {
                int id = tid + (i << 8);
                int r = id >> 2, c = id & 3;
                uint32_t d = stb + (uint32_t)(r * 80 + c * 16);
                cpasync16(d + ST_BH, pBh + (size_t)r * K + k0 + c * 8);
                cpasync16(d + ST_BM, pBm + (size_t)r * K + k0 + c * 8);
            }
        }
        asm volatile("cp.async.commit_group;" ::: "memory");
        asm volatile("cp.async.wait_group 1;" ::: "memory");
        __syncthreads();

        const uint32_t stb = sb + (uint32_t)((kt & 1) * STAGE);
        #pragma unroll
        for (int kk = 0; kk < 2; kk++) {          // two k16 steps of BK=32
            uint32_t ah[4][4], am[4][4];
            #pragma unroll
            for (int mf = 0; mf < 4; mf++) {
                uint32_t o = aOff + (uint32_t)(mf * 1280 + kk * 32);
                ldsm4(ah[mf], stb + ST_AH + o);
                ldsm4(am[mf], stb + ST_AM + o);
            }
            #pragma unroll
            for (int p = 0; p < 4; p++) {          // pairs of n-frags (16 cols)
                uint32_t bh[4], bm[4];
                uint32_t o = bOff + (uint32_t)(p * 1280 + kk * 32);
                ldsm4(bh, stb + ST_BH + o);
                ldsm4(bm, stb + ST_BM + o);
                #pragma unroll
                for (int mf = 0; mf < 4; mf++) {
                    mma16(acc[mf][2 * p],     ah[mf], bh[0], bh[2]);   // hi*hi
                    mma16(acc[mf][2 * p],     ah[mf], bm[0], bm[2]);   // hi*mid
                    mma16(acc[mf][2 * p],     am[mf], bh[0], bh[2]);   // mid*hi
                    mma16(acc[mf][2 * p + 1], ah[mf], bh[1], bh[3]);
                    mma16(acc[mf][2 * p + 1], ah[mf], bm[1], bm[3]);
                    mma16(acc[mf][2 * p + 1], am[mf], bh[1], bh[3]);
                }
            }
        }
        __syncthreads();
    }

    // -------- epilogue --------
    float* Cb = C + (size_t)bz * batC;
    #pragma unroll
    for (int mf = 0; mf < 4; mf++) {
        int r0 = bM + wm + mf * 16 + gp;
        #pragma unroll
        for (int nf = 0; nf < 8; nf++) {
            int c0 = bN + wn + nf * 8 + 2 * tg;
            *reinterpret_cast<float2*>(Cb + (size_t)r0 * ldc + c0) =
                make_float2(acc[mf][nf][0], acc[mf][nf][1]);
            *reinterpret_cast<float2*>(Cb + (size_t)(r0 + 8) * ldc + c0) =
                make_float2(acc[mf][nf][2], acc[mf][nf][3]);
        }
    }
}

// ============================================================================
// softmax over contiguous s, writes P as bf16 hi/mid
// ============================================================================
__global__ void __launch_bounds__(256)
softmax_kernel() {
    __shared__ float red[8];
    const size_t row = blockIdx.x;
    const float* S = g_scores + row * TS;
    const int tid = threadIdx.x;

    float x[8];
    float4 v0 = *reinterpret_cast<const float4*>(S + tid * 8);
    float4 v1 = *reinterpret_cast<const float4*>(S + tid * 8 + 4);
    x[0] = v0.x; x[1] = v0.y; x[2] = v0.z; x[3] = v0.w;
    x[4] = v1.x; x[5] = v1.y; x[6] = v1.z; x[7] = v1.w;

    float m = x[0];
    #pragma unroll
    for (int j = 1; j < 8; j++) m = fmaxf(m, x[j]);
    #pragma unroll
    for (int o = 16; o > 0; o >>= 1) m = fmaxf(m, __shfl_xor_sync(0xffffffffu, m, o));
    if ((tid & 31) == 0) red[tid >> 5] = m;
    __syncthreads();
    float mm = red[0];
    #pragma unroll
    for (int i = 1; i < 8; i++) mm = fmaxf(mm, red[i]);
    __syncthreads();

    float s = 0.f;
    #pragma unroll
    for (int j = 0; j < 8; j++) { x[j] = __expf(x[j] - mm); s += x[j]; }
    #pragma unroll
    for (int o = 16; o > 0; o >>= 1) s += __shfl_xor_sync(0xffffffffu, s, o);
    if ((tid & 31) == 0) red[tid >> 5] = s;
    __syncthreads();
    float tot = 0.f;
    #pragma unroll
    for (int i = 0; i < 8; i++) tot += red[i];
    float inv = 1.f / tot;
    #pragma unroll
    for (int j = 0; j < 8; j++) x[j] *= inv;

    uint2 h0, m0, h1, m1;
    split4(make_float4(x[0], x[1], x[2], x[3]), h0, m0);
    split4(make_float4(x[4], x[5], x[6], x[7]), h1, m1);
    size_t o = row * TS + (size_t)tid * 8;
    *reinterpret_cast<uint4*>(g_Ph + o) = make_uint4(h0.x, h0.y, h1.x, h1.y);
    *reinterpret_cast<uint4*>(g_Pm + o) = make_uint4(m0.x, m0.y, m1.x, m1.y);
}

// ============================================================================
// launch
// ============================================================================
extern "C" void kernel_launch(void* const* d_in, const int* in_sizes, int n_in,
                              void* d_out, int out_size) {
    const float* hidden = (const float*)d_in[0];   // [NB, TQ, HD]
    const float* enc    = (const float*)d_in[1];   // [NB, TS, HD]
    float* out = (float*)d_out;                    // [NB, TQ, HD]

    cudaFuncSetAttribute(gemm_kernel, cudaFuncAttributeMaxDynamicSharedMemorySize, GEMM_SMEM);

    void *pHh, *pHm, *pEh, *pEm, *pETh, *pETm, *pPh, *pPm, *pS;
    cudaGetSymbolAddress(&pHh, g_Hh);
    cudaGetSymbolAddress(&pHm, g_Hm);
    cudaGetSymbolAddress(&pEh, g_Eh);
    cudaGetSymbolAddress(&pEm, g_Em);
    cudaGetSymbolAddress(&pETh, g_ETh);
    cudaGetSymbolAddress(&pETm, g_ETm);
    cudaGetSymbolAddress(&pPh, g_Ph);
    cudaGetSymbolAddress(&pPm, g_Pm);
    cudaGetSymbolAddress(&pS, g_scores);

    // prep
    convert_kernel<<<((size_t)NB * TQ * HD) / 1024, 256>>>(hidden, enc);
    transpose_kernel<<<dim3(TS / 32, HD / 32, NB), 256>>>(enc);

    // K1: scores[q,s] = hid . enc   (M=q, N=s, K=h)
    gemm_kernel<<<dim3(TS / 256, TQ / 128, NB), 256, GEMM_SMEM>>>(
        (const __nv_bfloat16*)pHh, (const __nv_bfloat16*)pHm,
        (const __nv_bfloat16*)pEh, (const __nv_bfloat16*)pEm,
        (float*)pS, HD, TS,
        (size_t)TQ * HD, (size_t)TS * HD, (size_t)TQ * TS);

    // K2: softmax over s, emit P hi/mid
    softmax_kernel<<<NB * TQ, 256>>>();

    // K3: context[q,h] = P . encT   (M=q, N=h, K=s)
    gemm_kernel<<<dim3(HD / 256, TQ / 128, NB), 256, GEMM_SMEM>>>(
        (const __nv_bfloat16*)pPh, (const __nv_bfloat16*)pPm,
        (const __nv_bfloat16*)pETh, (const __nv_bfloat16*)pETm,
        out, TS, HD,
        (size_t)TQ * TS, (size_t)HD * TS, (size_t)TQ * HD);
}

// round 9
// speedup vs baseline: 1.1706x; 1.1706x over previous
#include <cuda_runtime.h>
#include <cuda_bf16.h>
#include <cstdint>

// Problem shape (fixed by reference setup_inputs)
static constexpr int NB = 16;
static constexpr int TQ = 2048;
static constexpr int TS = 2048;
static constexpr int HD = 1024;

// ---------------------------------------------------------------------------
// Static device scratch (no allocations allowed)
// ---------------------------------------------------------------------------
__device__ float g_scores[(size_t)NB * TQ * TS];                    // 256 MB
__device__ __nv_bfloat16 g_Hh[(size_t)NB * TQ * HD];
__device__ __nv_bfloat16 g_Hm[(size_t)NB * TQ * HD];
__device__ __nv_bfloat16 g_Eh[(size_t)NB * TS * HD];
__device__ __nv_bfloat16 g_Em[(size_t)NB * TS * HD];
__device__ __nv_bfloat16 g_ETh[(size_t)NB * HD * TS];               // enc^T
__device__ __nv_bfloat16 g_ETm[(size_t)NB * HD * TS];
__device__ __nv_bfloat16 g_Ph[(size_t)NB * TQ * TS];
__device__ __nv_bfloat16 g_Pm[(size_t)NB * TQ * TS];

// ---------------------------------------------------------------------------
// helpers
// ---------------------------------------------------------------------------
__device__ __forceinline__ void split4(float4 v, uint2& hi, uint2& mid) {
    __nv_bfloat162 h01 = __floats2bfloat162_rn(v.x, v.y);
    __nv_bfloat162 h23 = __floats2bfloat162_rn(v.z, v.w);
    float2 f01 = __bfloat1622float2(h01);
    float2 f23 = __bfloat1622float2(h23);
    __nv_bfloat162 m01 = __floats2bfloat162_rn(v.x - f01.x, v.y - f01.y);
    __nv_bfloat162 m23 = __floats2bfloat162_rn(v.z - f23.x, v.w - f23.y);
    hi.x  = *reinterpret_cast<uint32_t*>(&h01);
    hi.y  = *reinterpret_cast<uint32_t*>(&h23);
    mid.x = *reinterpret_cast<uint32_t*>(&m01);
    mid.y = *reinterpret_cast<uint32_t*>(&m23);
}

__device__ __forceinline__ void cpasync16(uint32_t dst, const void* src) {
    asm volatile("cp.async.cg.shared.global [%0], [%1], 16;\n" :: "r"(dst), "l"(src));
}

__device__ __forceinline__ void mma16(float c[4], const uint32_t a[4],
                                      uint32_t b0, uint32_t b1) {
    asm volatile(
        "mma.sync.aligned.m16n8k16.row.col.f32.bf16.bf16.f32 "
        "{%0,%1,%2,%3}, {%4,%5,%6,%7}, {%8,%9}, {%0,%1,%2,%3};\n"
        : "+f"(c[0]), "+f"(c[1]), "+f"(c[2]), "+f"(c[3])
        : "r"(a[0]), "r"(a[1]), "r"(a[2]), "r"(a[3]), "r"(b0), "r"(b1));
}

__device__ __forceinline__ void ldsm4(uint32_t r[4], uint32_t addr) {
    asm volatile("ldmatrix.sync.aligned.m8n8.x4.shared.b16 {%0,%1,%2,%3}, [%4];"
                 : "=r"(r[0]), "=r"(r[1]), "=r"(r[2]), "=r"(r[3]) : "r"(addr));
}
__device__ __forceinline__ void ldsm2(uint32_t& r0, uint32_t& r1, uint32_t addr) {
    asm volatile("ldmatrix.sync.aligned.m8n8.x2.shared.b16 {%0,%1}, [%2];"
                 : "=r"(r0), "=r"(r1) : "r"(addr));
}

// ============================================================================
// prep: split hid/enc into bf16 hi+mid
// ============================================================================
__global__ void __launch_bounds__(256)
convert_kernel(const float* __restrict__ hid, const float* __restrict__ enc) {
    size_t i = ((size_t)blockIdx.x * 256 + threadIdx.x) * 4;
    float4 h = *reinterpret_cast<const float4*>(hid + i);
    uint2 hh, hm;
    split4(h, hh, hm);
    *reinterpret_cast<uint2*>(g_Hh + i) = hh;
    *reinterpret_cast<uint2*>(g_Hm + i) = hm;
    float4 e = *reinterpret_cast<const float4*>(enc + i);
    uint2 eh, em;
    split4(e, eh, em);
    *reinterpret_cast<uint2*>(g_Eh + i) = eh;
    *reinterpret_cast<uint2*>(g_Em + i) = em;
}

// ============================================================================
// prep: enc[b][s][h] -> encT hi/mid [b][h][s]   (K-major B operand for K3)
// ============================================================================
__global__ void __launch_bounds__(256)
transpose_kernel(const float* __restrict__ enc) {
    __shared__ float tile[32][33];
    const int b = blockIdx.z;
    const int s0 = blockIdx.x * 32, h0 = blockIdx.y * 32;
    const int tx = threadIdx.x & 31, ty = threadIdx.x >> 5;
    const float* src = enc + (size_t)b * TS * HD;
    #pragma unroll
    for (int j = 0; j < 32; j += 8)
        tile[ty + j][tx] = src[(size_t)(s0 + ty + j) * HD + h0 + tx];
    __syncthreads();
    #pragma unroll
    for (int j = 0; j < 32; j += 8) {
        int r = ty + j;                       // h_local
        float v = tile[tx][r];                // enc[s0+tx][h0+r]
        __nv_bfloat16 hb = __float2bfloat16(v);
        __nv_bfloat16 mb = __float2bfloat16(v - __bfloat162float(hb));
        size_t o = (size_t)b * HD * TS + (size_t)(h0 + r) * TS + s0 + tx;
        g_ETh[o] = hb;
        g_ETm[o] = mb;
    }
}

// ============================================================================
// generic mma.sync GEMM: C[M,N] = (Ah+Am)*(Bh+Bm)^T, 3 split terms.
// A: [M][K] K-contig, B: [N][K] K-contig, both pre-split bf16.
// Block tile 128x128, BK=32, 8 warps (2x4), warp tile 64x32. 2 CTAs/SM.
// smem rows padded to 80B; double-buffered cp.async pipeline.
// ============================================================================
static constexpr int ST_AH = 0;
static constexpr int ST_AM = 10240;    // 128*80
static constexpr int ST_BH = 20480;
static constexpr int ST_BM = 30720;
static constexpr int STAGE = 40960;
static constexpr int GEMM_SMEM = 2 * STAGE;   // 81920 -> 2 CTAs/SM

__global__ void __launch_bounds__(256, 2)
gemm_kernel(const __nv_bfloat16* __restrict__ Ah, const __nv_bfloat16* __restrict__ Am,
            const __nv_bfloat16* __restrict__ Bh, const __nv_bfloat16* __restrict__ Bm,
            float* __restrict__ C, int K, int ldc,
            size_t batA, size_t batB, size_t batC) {
    extern __shared__ __align__(128) char smem[];
    const uint32_t sb = (uint32_t)__cvta_generic_to_shared(smem);
    const int tid  = threadIdx.x;
    const int lane = tid & 31;
    const int wid  = tid >> 5;
    const int bz = blockIdx.z;
    const int bM = blockIdx.y * 128;
    const int bN = blockIdx.x * 128;
    const int wm = (wid >> 2) * 64;
    const int wn = (wid & 3) * 32;
    const int tg = lane & 3;
    const int gp = lane >> 2;

    const __nv_bfloat16* pAh = Ah + (size_t)bz * batA + (size_t)bM * K;
    const __nv_bfloat16* pAm = Am + (size_t)bz * batA + (size_t)bM * K;
    const __nv_bfloat16* pBh = Bh + (size_t)bz * batB + (size_t)bN * K;
    const __nv_bfloat16* pBm = Bm + (size_t)bz * batB + (size_t)bN * K;

    // ldmatrix per-lane base byte offsets (row-major padded tiles, 80B rows)
    const uint32_t aOff = (uint32_t)(wm + (lane & 15)) * 80u + (uint32_t)(lane >> 4) * 16u;
    const uint32_t bOff = (uint32_t)(wn + (lane & 7)) * 80u + (uint32_t)((lane >> 3) & 1) * 16u;

    float acc[4][4][4];
    #pragma unroll
    for (int i = 0; i < 4; i++)
        #pragma unroll
        for (int j = 0; j < 4; j++)
            #pragma unroll
            for (int k = 0; k < 4; k++) acc[i][j][k] = 0.f;

    const int KT = K >> 5;

    // gmem->smem mapping: per tensor 512 chunks of 16B, 2 per thread
    // id = tid + i*256 ; r = id>>2 (row 0..127), c = id&3 (16B chunk)
    // -------- prologue: prefetch tile 0 --------
    #pragma unroll
    for (int i = 0; i < 2; i++) {
        int id = tid + (i << 8);
        int r = id >> 2, c = id & 3;
        uint32_t d = sb + (uint32_t)(r * 80 + c * 16);
        size_t go = (size_t)r * K + c * 8;
        cpasync16(d + ST_AH, pAh + go);
        cpasync16(d + ST_AM, pAm + go);
        cpasync16(d + ST_BH, pBh + go);
        cpasync16(d + ST_BM, pBm + go);
    }
    asm volatile("cp.async.commit_group;" ::: "memory");

    for (int kt = 0; kt < KT; kt++) {
        // prefetch next tile into the other buffer
        if (kt + 1 < KT) {
            const int k0 = (kt + 1) << 5;
            const uint32_t stb = sb + (uint32_t)(((kt + 1) & 1) * STAGE);
            #pragma unroll
            for (int i = 0; i < 2; i++) {
                int id = tid + (i << 8);
                int r = id >> 2, c = id & 3;
                uint32_t d = stb + (uint32_t)(r * 80 + c * 16);
                size_t go = (size_t)r * K + k0 + c * 8;
                cpasync16(d + ST_AH, pAh + go);
                cpasync16(d + ST_AM, pAm + go);
                cpasync16(d + ST_BH, pBh + go);
                cpasync16(d + ST_BM, pBm + go);
            }
        }
        asm volatile("cp.async.commit_group;" ::: "memory");
        asm volatile("cp.async.wait_group 1;" ::: "memory");
        __syncthreads();

        const uint32_t stb = sb + (uint32_t)((kt & 1) * STAGE);
        #pragma unroll
        for (int kk = 0; kk < 2; kk++) {          // two k16 steps of BK=32
            uint32_t ah[4][4], am[4][4];
            #pragma unroll
            for (int mf = 0; mf < 4; mf++) {
                uint32_t o = aOff + (uint32_t)(mf * 1280 + kk * 32);
                ldsm4(ah[mf], stb + ST_AH + o);
                ldsm4(am[mf], stb + ST_AM + o);
            }
            #pragma unroll
            for (int nf = 0; nf < 4; nf++) {
                uint32_t bh0, bh1, bm0, bm1;
                uint32_t o = bOff + (uint32_t)(nf * 640 + kk * 32);
                ldsm2(bh0, bh1, stb + ST_BH + o);
                ldsm2(bm0, bm1, stb + ST_BM + o);
                #pragma unroll
                for (int mf = 0; mf < 4; mf++) {
                    mma16(acc[mf][nf], ah[mf], bh0, bh1);   // hi*hi
                    mma16(acc[mf][nf], ah[mf], bm0, bm1);   // hi*mid
                    mma16(acc[mf][nf], am[mf], bh0, bh1);   // mid*hi
                }
            }
        }
        __syncthreads();
    }

    // -------- epilogue --------
    float* Cb = C + (size_t)bz * batC;
    #pragma unroll
    for (int mf = 0; mf < 4; mf++) {
        int r0 = bM + wm + mf * 16 + gp;
        #pragma unroll
        for (int nf = 0; nf < 4; nf++) {
            int c0 = bN + wn + nf * 8 + 2 * tg;
            *reinterpret_cast<float2*>(Cb + (size_t)r0 * ldc + c0) =
                make_float2(acc[mf][nf][0], acc[mf][nf][1]);
            *reinterpret_cast<float2*>(Cb + (size_t)(r0 + 8) * ldc + c0) =
                make_float2(acc[mf][nf][2], acc[mf][nf][3]);
        }
    }
}

// ============================================================================
// softmax over contiguous s, writes P as bf16 hi/mid
// ============================================================================
__global__ void __launch_bounds__(256)
softmax_kernel() {
    __shared__ float red[8];
    const size_t row = blockIdx.x;
    const float* S = g_scores + row * TS;
    const int tid = threadIdx.x;

    float x[8];
    float4 v0 = *reinterpret_cast<const float4*>(S + tid * 8);
    float4 v1 = *reinterpret_cast<const float4*>(S + tid * 8 + 4);
    x[0] = v0.x; x[1] = v0.y; x[2] = v0.z; x[3] = v0.w;
    x[4] = v1.x; x[5] = v1.y; x[6] = v1.z; x[7] = v1.w;

    float m = x[0];
    #pragma unroll
    for (int j = 1; j < 8; j++) m = fmaxf(m, x[j]);
    #pragma unroll
    for (int o = 16; o > 0; o >>= 1) m = fmaxf(m, __shfl_xor_sync(0xffffffffu, m, o));
    if ((tid & 31) == 0) red[tid >> 5] = m;
    __syncthreads();
    float mm = red[0];
    #pragma unroll
    for (int i = 1; i < 8; i++) mm = fmaxf(mm, red[i]);
    __syncthreads();

    float s = 0.f;
    #pragma unroll
    for (int j = 0; j < 8; j++) { x[j] = __expf(x[j] - mm); s += x[j]; }
    #pragma unroll
    for (int o = 16; o > 0; o >>= 1) s += __shfl_xor_sync(0xffffffffu, s, o);
    if ((tid & 31) == 0) red[tid >> 5] = s;
    __syncthreads();
    float tot = 0.f;
    #pragma unroll
    for (int i = 0; i < 8; i++) tot += red[i];
    float inv = 1.f / tot;
    #pragma unroll
    for (int j = 0; j < 8; j++) x[j] *= inv;

    uint2 h0, m0, h1, m1;
    split4(make_float4(x[0], x[1], x[2], x[3]), h0, m0);
    split4(make_float4(x[4], x[5], x[6], x[7]), h1, m1);
    size_t o = row * TS + (size_t)tid * 8;
    *reinterpret_cast<uint4*>(g_Ph + o) = make_uint4(h0.x, h0.y, h1.x, h1.y);
    *reinterpret_cast<uint4*>(g_Pm + o) = make_uint4(m0.x, m0.y, m1.x, m1.y);
}

// ============================================================================
// launch
// ============================================================================
extern "C" void kernel_launch(void* const* d_in, const int* in_sizes, int n_in,
                              void* d_out, int out_size) {
    const float* hidden = (const float*)d_in[0];   // [NB, TQ, HD]
    const float* enc    = (const float*)d_in[1];   // [NB, TS, HD]
    float* out = (float*)d_out;                    // [NB, TQ, HD]

    cudaFuncSetAttribute(gemm_kernel, cudaFuncAttributeMaxDynamicSharedMemorySize, GEMM_SMEM);

    void *pHh, *pHm, *pEh, *pEm, *pETh, *pETm, *pPh, *pPm, *pS;
    cudaGetSymbolAddress(&pHh, g_Hh);
    cudaGetSymbolAddress(&pHm, g_Hm);
    cudaGetSymbolAddress(&pEh, g_Eh);
    cudaGetSymbolAddress(&pEm, g_Em);
    cudaGetSymbolAddress(&pETh, g_ETh);
    cudaGetSymbolAddress(&pETm, g_ETm);
    cudaGetSymbolAddress(&pPh, g_Ph);
    cudaGetSymbolAddress(&pPm, g_Pm);
    cudaGetSymbolAddress(&pS, g_scores);

    // prep
    convert_kernel<<<((size_t)NB * TQ * HD) / 1024, 256>>>(hidden, enc);
    transpose_kernel<<<dim3(TS / 32, HD / 32, NB), 256>>>(enc);

    // K1: scores[q,s] = hid . enc   (M=q, N=s, K=h)
    gemm_kernel<<<dim3(TS / 128, TQ / 128, NB), 256, GEMM_SMEM>>>(
        (const __nv_bfloat16*)pHh, (const __nv_bfloat16*)pHm,
        (const __nv_bfloat16*)pEh, (const __nv_bfloat16*)pEm,
        (float*)pS, HD, TS,
        (size_t)TQ * HD, (size_t)TS * HD, (size_t)TQ * TS);

    // K2: softmax over s, emit P hi/mid
    softmax_kernel<<<NB * TQ, 256>>>();

    // K3: context[q,h] = P . encT   (M=q, N=h, K=s)
    gemm_kernel<<<dim3(HD / 128, TQ / 128, NB), 256, GEMM_SMEM>>>(
        (const __nv_bfloat16*)pPh, (const __nv_bfloat16*)pPm,
        (const __nv_bfloat16*)pETh, (const __nv_bfloat16*)pETm,
        out, TS, HD,
        (size_t)TQ * TS, (size_t)HD * TS, (size_t)TQ * HD);
}

// round 13
// speedup vs baseline: 1.2400x; 1.0593x over previous
#include <cuda_runtime.h>
#include <cuda_bf16.h>
#include <cstdint>

// Problem shape (fixed by reference setup_inputs)
static constexpr int NB = 16;
static constexpr int TQ = 2048;
static constexpr int TS = 2048;
static constexpr int HD = 1024;

// ---------------------------------------------------------------------------
// Static device scratch (no allocations allowed)
// ---------------------------------------------------------------------------
__device__ float g_scores[(size_t)NB * TQ * TS];                    // 256 MB
__device__ __nv_bfloat16 g_Hh[(size_t)NB * TQ * HD];
__device__ __nv_bfloat16 g_Hm[(size_t)NB * TQ * HD];
__device__ __nv_bfloat16 g_Eh[(size_t)NB * TS * HD];
__device__ __nv_bfloat16 g_Em[(size_t)NB * TS * HD];
__device__ __nv_bfloat16 g_ETh[(size_t)NB * HD * TS];               // enc^T
__device__ __nv_bfloat16 g_ETm[(size_t)NB * HD * TS];
__device__ __nv_bfloat16 g_Ph[(size_t)NB * TQ * TS];
__device__ __nv_bfloat16 g_Pm[(size_t)NB * TQ * TS];

// ---------------------------------------------------------------------------
// helpers
// ---------------------------------------------------------------------------
__device__ __forceinline__ void split4(float4 v, uint2& hi, uint2& mid) {
    __nv_bfloat162 h01 = __floats2bfloat162_rn(v.x, v.y);
    __nv_bfloat162 h23 = __floats2bfloat162_rn(v.z, v.w);
    float2 f01 = __bfloat1622float2(h01);
    float2 f23 = __bfloat1622float2(h23);
    __nv_bfloat162 m01 = __floats2bfloat162_rn(v.x - f01.x, v.y - f01.y);
    __nv_bfloat162 m23 = __floats2bfloat162_rn(v.z - f23.x, v.w - f23.y);
    hi.x  = *reinterpret_cast<uint32_t*>(&h01);
    hi.y  = *reinterpret_cast<uint32_t*>(&h23);
    mid.x = *reinterpret_cast<uint32_t*>(&m01);
    mid.y = *reinterpret_cast<uint32_t*>(&m23);
}

__device__ __forceinline__ void cpasync16(uint32_t dst, const void* src) {
    asm volatile("cp.async.cg.shared.global [%0], [%1], 16;\n" :: "r"(dst), "l"(src));
}

__device__ __forceinline__ void mma16(float c[4], const uint32_t a[4],
                                      uint32_t b0, uint32_t b1) {
    asm volatile(
        "mma.sync.aligned.m16n8k16.row.col.f32.bf16.bf16.f32 "
        "{%0,%1,%2,%3}, {%4,%5,%6,%7}, {%8,%9}, {%0,%1,%2,%3};\n"
        : "+f"(c[0]), "+f"(c[1]), "+f"(c[2]), "+f"(c[3])
        : "r"(a[0]), "r"(a[1]), "r"(a[2]), "r"(a[3]), "r"(b0), "r"(b1));
}

__device__ __forceinline__ void ldsm4(uint32_t r[4], uint32_t addr) {
    asm volatile("ldmatrix.sync.aligned.m8n8.x4.shared.b16 {%0,%1,%2,%3}, [%4];"
                 : "=r"(r[0]), "=r"(r[1]), "=r"(r[2]), "=r"(r[3]) : "r"(addr));
}

// ============================================================================
// prep: split hidden into bf16 hi+mid (enc handled by transpose_kernel)
// ============================================================================
__global__ void __launch_bounds__(256)
convert_kernel(const float* __restrict__ hid) {
    size_t i = ((size_t)blockIdx.x * 256 + threadIdx.x) * 4;
    float4 h = *reinterpret_cast<const float4*>(hid + i);
    uint2 hh, hm;
    split4(h, hh, hm);
    *reinterpret_cast<uint2*>(g_Hh + i) = hh;
    *reinterpret_cast<uint2*>(g_Hm + i) = hm;
}

// ============================================================================
// prep: enc -> Eh/Em (row-major limbs) AND ETh/ETm (transposed limbs)
// ============================================================================
__global__ void __launch_bounds__(256)
transpose_kernel(const float* __restrict__ enc) {
    __shared__ float tile[32][33];
    const int b = blockIdx.z;
    const int s0 = blockIdx.x * 32, h0 = blockIdx.y * 32;
    const int tx = threadIdx.x & 31, ty = threadIdx.x >> 5;
    const float* src = enc + (size_t)b * TS * HD;
    #pragma unroll
    for (int j = 0; j < 32; j += 8) {
        size_t o = (size_t)(s0 + ty + j) * HD + h0 + tx;
        float v = src[o];
        tile[ty + j][tx] = v;
        __nv_bfloat16 hb = __float2bfloat16(v);
        __nv_bfloat16 mb = __float2bfloat16(v - __bfloat162float(hb));
        size_t go = (size_t)b * TS * HD + o;
        g_Eh[go] = hb;
        g_Em[go] = mb;
    }
    __syncthreads();
    #pragma unroll
    for (int j = 0; j < 32; j += 8) {
        int r = ty + j;                       // h_local
        float v = tile[tx][r];                // enc[s0+tx][h0+r]
        __nv_bfloat16 hb = __float2bfloat16(v);
        __nv_bfloat16 mb = __float2bfloat16(v - __bfloat162float(hb));
        size_t o = (size_t)b * HD * TS + (size_t)(h0 + r) * TS + s0 + tx;
        g_ETh[o] = hb;
        g_ETm[o] = mb;
    }
}

// ============================================================================
// generic mma.sync GEMM: C[M,N] = (Ah+Am)*(Bh+Bm)^T, 3 split terms.
// A: [M][K] K-contig, B: [N][K] K-contig, both pre-split bf16.
// Block tile 128x128, BK=32, 8 warps (2x4), warp tile 64x32. 2 CTAs/SM.
// smem rows padded to 80B; double-buffered cp.async, two barriers per k-tile
// (after wait_group: data published to all; after compute: buffer reusable).
// B fragments loaded as paired ldsm4 (two n-blocks per instruction).
// ============================================================================
static constexpr int ST_AH = 0;
static constexpr int ST_AM = 10240;    // 128*80
static constexpr int ST_BH = 20480;
static constexpr int ST_BM = 30720;
static constexpr int STAGE = 40960;
static constexpr int GEMM_SMEM = 2 * STAGE;   // 81920 -> 2 CTAs/SM

__global__ void __launch_bounds__(256, 2)
gemm_kernel(const __nv_bfloat16* __restrict__ Ah, const __nv_bfloat16* __restrict__ Am,
            const __nv_bfloat16* __restrict__ Bh, const __nv_bfloat16* __restrict__ Bm,
            float* __restrict__ C, int K, int ldc,
            size_t batA, size_t batB, size_t batC) {
    extern __shared__ __align__(128) char smem[];
    const uint32_t sb = (uint32_t)__cvta_generic_to_shared(smem);
    const int tid  = threadIdx.x;
    const int lane = tid & 31;
    const int wid  = tid >> 5;
    const int bz = blockIdx.z;
    const int bM = blockIdx.y * 128;
    const int bN = blockIdx.x * 128;
    const int wm = (wid >> 2) * 64;
    const int wn = (wid & 3) * 32;
    const int tg = lane & 3;
    const int gp = lane >> 2;

    const __nv_bfloat16* pAh = Ah + (size_t)bz * batA + (size_t)bM * K;
    const __nv_bfloat16* pAm = Am + (size_t)bz * batA + (size_t)bM * K;
    const __nv_bfloat16* pBh = Bh + (size_t)bz * batB + (size_t)bN * K;
    const __nv_bfloat16* pBm = Bm + (size_t)bz * batB + (size_t)bN * K;

    // ldmatrix per-lane base byte offsets (row-major padded tiles, 80B rows)
    // A x4: lanes 0-15 -> 16 rows, lane>>4 -> k-half
    const uint32_t aOff = (uint32_t)(wm + (lane & 15)) * 80u + (uint32_t)(lane >> 4) * 16u;
    // B paired x4: lanes 0-15 -> n-block 2p (k-halves), lanes 16-31 -> n-block 2p+1
    const uint32_t bOff = (uint32_t)(wn + ((lane >> 4) << 3) + (lane & 7)) * 80u
                        + (uint32_t)((lane >> 3) & 1) * 16u;

    float acc[4][4][4];
    #pragma unroll
    for (int i = 0; i < 4; i++)
        #pragma unroll
        for (int j = 0; j < 4; j++)
            #pragma unroll
            for (int k = 0; k < 4; k++) acc[i][j][k] = 0.f;

    const int KT = K >> 5;

    // gmem->smem mapping: per tensor 512 chunks of 16B, 2 per thread
    // -------- prologue: prefetch tile 0 into buffer 0 --------
    #pragma unroll
    for (int i = 0; i < 2; i++) {
        int id = tid + (i << 8);
        int r = id >> 2, c = id & 3;
        uint32_t d = sb + (uint32_t)(r * 80 + c * 16);
        size_t go = (size_t)r * K + c * 8;
        cpasync16(d + ST_AH, pAh + go);
        cpasync16(d + ST_AM, pAm + go);
        cpasync16(d + ST_BH, pBh + go);
        cpasync16(d + ST_BM, pBm + go);
    }
    asm volatile("cp.async.commit_group;" ::: "memory");

    for (int kt = 0; kt < KT; kt++) {
        // prefetch next tile into the other buffer (safe: barrier at end of
        // previous iteration guarantees all warps finished reading it)
        if (kt + 1 < KT) {
            const int k0 = (kt + 1) << 5;
            const uint32_t stb = sb + (uint32_t)(((kt + 1) & 1) * STAGE);
            #pragma unroll
            for (int i = 0; i < 2; i++) {
                int id = tid + (i << 8);
                int r = id >> 2, c = id & 3;
                uint32_t d = stb + (uint32_t)(r * 80 + c * 16);
                size_t go = (size_t)r * K + k0 + c * 8;
                cpasync16(d + ST_AH, pAh + go);
                cpasync16(d + ST_AM, pAm + go);
                cpasync16(d + ST_BH, pBh + go);
                cpasync16(d + ST_BM, pBm + go);
            }
        }
        asm volatile("cp.async.commit_group;" ::: "memory");
        asm volatile("cp.async.wait_group 1;" ::: "memory");  // own tile-kt copies done
        __syncthreads();                                       // publish to all warps

        const uint32_t stb = sb + (uint32_t)((kt & 1) * STAGE);
        #pragma unroll
        for (int kk = 0; kk < 2; kk++) {          // two k16 steps of BK=32
            uint32_t ah[4][4], am[4][4];
            #pragma unroll
            for (int mf = 0; mf < 4; mf++) {
                uint32_t o = aOff + (uint32_t)(mf * 1280 + kk * 32);
                ldsm4(ah[mf], stb + ST_AH + o);
                ldsm4(am[mf], stb + ST_AM + o);
            }
            #pragma unroll
            for (int p = 0; p < 2; p++) {          // n-block pairs (2p, 2p+1)
                uint32_t bh[4], bm[4];
                uint32_t o = bOff + (uint32_t)(p * 1280 + kk * 32);
                ldsm4(bh, stb + ST_BH + o);
                ldsm4(bm, stb + ST_BM + o);
                // term-outer ordering: per-accumulator sequence stays hh,hm,mh
                #pragma unroll
                for (int mf = 0; mf < 4; mf++) {
                    mma16(acc[mf][2 * p],     ah[mf], bh[0], bh[1]);
                    mma16(acc[mf][2 * p + 1], ah[mf], bh[2], bh[3]);
                }
                #pragma unroll
                for (int mf = 0; mf < 4; mf++) {
                    mma16(acc[mf][2 * p],     ah[mf], bm[0], bm[1]);
                    mma16(acc[mf][2 * p + 1], ah[mf], bm[2], bm[3]);
                }
                #pragma unroll
                for (int mf = 0; mf < 4; mf++) {
                    mma16(acc[mf][2 * p],     am[mf], bh[0], bh[1]);
                    mma16(acc[mf][2 * p + 1], am[mf], bh[2], bh[3]);
                }
            }
        }
        __syncthreads();   // all warps done reading buffer kt&1 -> reusable
    }

    // -------- epilogue --------
    float* Cb = C + (size_t)bz * batC;
    #pragma unroll
    for (int mf = 0; mf < 4; mf++) {
        int r0 = bM + wm + mf * 16 + gp;
        #pragma unroll
        for (int nf = 0; nf < 4; nf++) {
            int c0 = bN + wn + nf * 8 + 2 * tg;
            *reinterpret_cast<float2*>(Cb + (size_t)r0 * ldc + c0) =
                make_float2(acc[mf][nf][0], acc[mf][nf][1]);
            *reinterpret_cast<float2*>(Cb + (size_t)(r0 + 8) * ldc + c0) =
                make_float2(acc[mf][nf][2], acc[mf][nf][3]);
        }
    }
}

// ============================================================================
// softmax over contiguous s, writes P as bf16 hi/mid
// ============================================================================
__global__ void __launch_bounds__(256)
softmax_kernel() {
    __shared__ float red[8];
    const size_t row = blockIdx.x;
    const float* S = g_scores + row * TS;
    const int tid = threadIdx.x;

    float x[8];
    float4 v0 = *reinterpret_cast<const float4*>(S + tid * 8);
    float4 v1 = *reinterpret_cast<const float4*>(S + tid * 8 + 4);
    x[0] = v0.x; x[1] = v0.y; x[2] = v0.z; x[3] = v0.w;
    x[4] = v1.x; x[5] = v1.y; x[6] = v1.z; x[7] = v1.w;

    float m = x[0];
    #pragma unroll
    for (int j = 1; j < 8; j++) m = fmaxf(m, x[j]);
    #pragma unroll
    for (int o = 16; o > 0; o >>= 1) m = fmaxf(m, __shfl_xor_sync(0xffffffffu, m, o));
    if ((tid & 31) == 0) red[tid >> 5] = m;
    __syncthreads();
    float mm = red[0];
    #pragma unroll
    for (int i = 1; i < 8; i++) mm = fmaxf(mm, red[i]);
    __syncthreads();

    float s = 0.f;
    #pragma unroll
    for (int j = 0; j < 8; j++) { x[j] = __expf(x[j] - mm); s += x[j]; }
    #pragma unroll
    for (int o = 16; o > 0; o >>= 1) s += __shfl_xor_sync(0xffffffffu, s, o);
    if ((tid & 31) == 0) red[tid >> 5] = s;
    __syncthreads();
    float tot = 0.f;
    #pragma unroll
    for (int i = 0; i < 8; i++) tot += red[i];
    float inv = 1.f / tot;
    #pragma unroll
    for (int j = 0; j < 8; j++) x[j] *= inv;

    uint2 h0, m0, h1, m1;
    split4(make_float4(x[0], x[1], x[2], x[3]), h0, m0);
    split4(make_float4(x[4], x[5], x[6], x[7]), h1, m1);
    size_t o = row * TS + (size_t)tid * 8;
    *reinterpret_cast<uint4*>(g_Ph + o) = make_uint4(h0.x, h0.y, h1.x, h1.y);
    *reinterpret_cast<uint4*>(g_Pm + o) = make_uint4(m0.x, m0.y, m1.x, m1.y);
}

// ============================================================================
// launch
// ============================================================================
extern "C" void kernel_launch(void* const* d_in, const int* in_sizes, int n_in,
                              void* d_out, int out_size) {
    const float* hidden = (const float*)d_in[0];   // [NB, TQ, HD]
    const float* enc    = (const float*)d_in[1];   // [NB, TS, HD]
    float* out = (float*)d_out;                    // [NB, TQ, HD]

    cudaFuncSetAttribute(gemm_kernel, cudaFuncAttributeMaxDynamicSharedMemorySize, GEMM_SMEM);

    void *pHh, *pHm, *pEh, *pEm, *pETh, *pETm, *pPh, *pPm, *pS;
    cudaGetSymbolAddress(&pHh, g_Hh);
    cudaGetSymbolAddress(&pHm, g_Hm);
    cudaGetSymbolAddress(&pEh, g_Eh);
    cudaGetSymbolAddress(&pEm, g_Em);
    cudaGetSymbolAddress(&pETh, g_ETh);
    cudaGetSymbolAddress(&pETm, g_ETm);
    cudaGetSymbolAddress(&pPh, g_Ph);
    cudaGetSymbolAddress(&pPm, g_Pm);
    cudaGetSymbolAddress(&pS, g_scores);

    // prep
    convert_kernel<<<((size_t)NB * TQ * HD) / 1024, 256>>>(hidden);
    transpose_kernel<<<dim3(TS / 32, HD / 32, NB), 256>>>(enc);

    // K1: scores[q,s] = hid . enc   (M=q, N=s, K=h)
    gemm_kernel<<<dim3(TS / 128, TQ / 128, NB), 256, GEMM_SMEM>>>(
        (const __nv_bfloat16*)pHh, (const __nv_bfloat16*)pHm,
        (const __nv_bfloat16*)pEh, (const __nv_bfloat16*)pEm,
        (float*)pS, HD, TS,
        (size_t)TQ * HD, (size_t)TS * HD, (size_t)TQ * TS);

    // K2: softmax over s, emit P hi/mid
    softmax_kernel<<<NB * TQ, 256>>>();

    // K3: context[q,h] = P . encT   (M=q, N=h, K=s)
    gemm_kernel<<<dim3(HD / 128, TQ / 128, NB), 256, GEMM_SMEM>>>(
        (const __nv_bfloat16*)pPh, (const __nv_bfloat16*)pPm,
        (const __nv_bfloat16*)pETh, (const __nv_bfloat16*)pETm,
        out, TS, HD,
        (size_t)TQ * TS, (size_t)HD * TS, (size_t)TQ * HD);
}